// round 1
// baseline (speedup 1.0000x reference)
#include <cuda_runtime.h>
#include <math.h>

#define NB    8
#define NSEQ  1024
#define HIDD  768
#define NH    12
#define LR    256
#define HD    64

// Scratch (no cudaMalloc allowed)
__device__ float g_Wc[NH * HD * HIDD];      // [h][e][d]  combined LoRA weight: Wa @ Wt
__device__ float g_t[NB * NH * NSEQ * HD];  // [b][h][n][e] projected tokens (q=k=v)

// ---------------------------------------------------------------------------
// Kernel 1: Wc[h][e][d] = sum_l Wa[h][e][l] * Wt[h][l][d]
// grid (12 heads, 6 d-chunks of 128), 256 threads, K-tile 32
// ---------------------------------------------------------------------------
__global__ __launch_bounds__(256) void k_wc(const float* __restrict__ Wt,
                                            const float* __restrict__ Wa) {
    const int h  = blockIdx.x;
    const int d0 = blockIdx.y * 128;
    __shared__ float Wa_s[64 * 36];    // [e][l] pad 36
    __shared__ float Wt_s[32 * 132];   // [l][d] pad 132

    const int tid = threadIdx.x;
    const int te = tid / 16;           // 16 groups of 4 e-rows
    const int td = tid % 16;           // 16 groups of 8 d-cols

    float acc[4][8];
#pragma unroll
    for (int i = 0; i < 4; i++)
#pragma unroll
        for (int j = 0; j < 8; j++) acc[i][j] = 0.f;

    for (int l0 = 0; l0 < LR; l0 += 32) {
        // Wa tile 64x32 -> 512 float4, 2 per thread
#pragma unroll
        for (int it = 0; it < 2; it++) {
            int f = tid + it * 256;
            int e = f / 8, l4 = f % 8;
            float4 v = *(const float4*)&Wa[((size_t)h * 64 + e) * LR + l0 + l4 * 4];
            *(float4*)&Wa_s[e * 36 + l4 * 4] = v;
        }
        // Wt tile 32x128 -> 1024 float4, 4 per thread
#pragma unroll
        for (int it = 0; it < 4; it++) {
            int f = tid + it * 256;
            int l = f / 32, d4 = f % 32;
            float4 v = *(const float4*)&Wt[((size_t)h * LR + l0 + l) * HIDD + d0 + d4 * 4];
            *(float4*)&Wt_s[l * 132 + d4 * 4] = v;
        }
        __syncthreads();
#pragma unroll
        for (int l = 0; l < 32; l++) {
            float a[4];
#pragma unroll
            for (int i = 0; i < 4; i++) a[i] = Wa_s[(te * 4 + i) * 36 + l];
            float w[8];
            *(float4*)&w[0] = *(const float4*)&Wt_s[l * 132 + td * 8];
            *(float4*)&w[4] = *(const float4*)&Wt_s[l * 132 + td * 8 + 4];
#pragma unroll
            for (int i = 0; i < 4; i++)
#pragma unroll
                for (int j = 0; j < 8; j++) acc[i][j] = fmaf(a[i], w[j], acc[i][j]);
        }
        __syncthreads();
    }
#pragma unroll
    for (int i = 0; i < 4; i++) {
        float4 o0 = make_float4(acc[i][0], acc[i][1], acc[i][2], acc[i][3]);
        float4 o1 = make_float4(acc[i][4], acc[i][5], acc[i][6], acc[i][7]);
        size_t base = ((size_t)h * HD + te * 4 + i) * HIDD + d0 + td * 8;
        *(float4*)&g_Wc[base]     = o0;
        *(float4*)&g_Wc[base + 4] = o1;
    }
}

// ---------------------------------------------------------------------------
// Kernel 2: t[b,h,n,e] = sum_d X[b,n,d] * Wc[h,e,d]
// grid (8 n-tiles of 128, 96 bh), 256 threads, K-tile 32, micro 8x4
// ---------------------------------------------------------------------------
__global__ __launch_bounds__(256) void k_proj(const float* __restrict__ X) {
    const int bh = blockIdx.y;
    const int b = bh / NH, h = bh % NH;
    const int n0 = blockIdx.x * 128;

    __shared__ float Xs[128 * 36];   // [r][k] pad 36
    __shared__ float Ws[32 * 68];    // [k][e] transposed, pad 68

    const int tid = threadIdx.x;
    const int trow = tid / 16;   // 16 groups of 8 rows
    const int tcol = tid % 16;   // 16 groups of 4 cols (e)

    float acc[8][4];
#pragma unroll
    for (int i = 0; i < 8; i++)
#pragma unroll
        for (int j = 0; j < 4; j++) acc[i][j] = 0.f;

    const float* Xbase = X + ((size_t)b * NSEQ + n0) * HIDD;
    const float* Wbase = g_Wc + (size_t)h * HD * HIDD;

    for (int k0 = 0; k0 < HIDD; k0 += 32) {
        // X tile 128x32 -> 1024 float4, 4/thread
#pragma unroll
        for (int it = 0; it < 4; it++) {
            int f = tid + it * 256;
            int r = f / 8, k4 = f % 8;
            float4 v = *(const float4*)&Xbase[(size_t)r * HIDD + k0 + k4 * 4];
            *(float4*)&Xs[r * 36 + k4 * 4] = v;
        }
        // W tile 64x32 transposed to [k][e] -> 512 float4, 2/thread
#pragma unroll
        for (int it = 0; it < 2; it++) {
            int f = tid + it * 256;
            int e = f / 8, k4 = f % 8;
            float4 v = *(const float4*)&Wbase[(size_t)e * HIDD + k0 + k4 * 4];
            Ws[(k4 * 4 + 0) * 68 + e] = v.x;
            Ws[(k4 * 4 + 1) * 68 + e] = v.y;
            Ws[(k4 * 4 + 2) * 68 + e] = v.z;
            Ws[(k4 * 4 + 3) * 68 + e] = v.w;
        }
        __syncthreads();
#pragma unroll
        for (int kk = 0; kk < 32; kk++) {
            float w[4];
            *(float4*)w = *(const float4*)&Ws[kk * 68 + tcol * 4];
            float x[8];
#pragma unroll
            for (int i = 0; i < 8; i++) x[i] = Xs[(trow * 8 + i) * 36 + kk];
#pragma unroll
            for (int i = 0; i < 8; i++)
#pragma unroll
                for (int j = 0; j < 4; j++) acc[i][j] = fmaf(x[i], w[j], acc[i][j]);
        }
        __syncthreads();
    }
#pragma unroll
    for (int i = 0; i < 8; i++) {
        float4 o = make_float4(acc[i][0], acc[i][1], acc[i][2], acc[i][3]);
        *(float4*)&g_t[((size_t)bh * NSEQ + n0 + trow * 8 + i) * HD + tcol * 4] = o;
    }
}

// ---------------------------------------------------------------------------
// Kernel 3: flash attention per (b,h). Q=K=V=t[b,h] [1024,64].
// grid (16 q-tiles of 64, 96 bh), 256 threads.
// Thread layout: trow=tid/16 owns rows trow*4+i; score cols = tcol+16*j;
// output cols e = tcol*4+j. Online softmax across 16 key tiles of 64.
// ---------------------------------------------------------------------------
__global__ __launch_bounds__(256) void k_attn(const int* __restrict__ amask,
                                              float* __restrict__ out) {
    extern __shared__ float sm[];
    float* Qs = sm;               // 64*64
    float* Ks = Qs + 64 * 64;     // 64*68 (pad for conflict-free float4)
    float* Ps = Ks + 64 * 68;     // 64*64
    int*   mk = (int*)(Ps + 64 * 64);  // 64

    const int bh = blockIdx.y;
    const int b = bh / NH, h = bh % NH;
    const int q0 = blockIdx.x * 64;
    const int tid = threadIdx.x;
    const int trow = tid / 16;
    const int tcol = tid % 16;

    const float* T = g_t + (size_t)bh * NSEQ * HD;
    const float scale = 0.03608439182435161f;  // 768^-0.5

    // Load Q tile, pre-scaled
#pragma unroll
    for (int it = 0; it < 4; it++) {
        int f = tid + it * 256;
        int r = f / 16, e4 = f % 16;
        float4 v = *(const float4*)&T[(size_t)(q0 + r) * HD + e4 * 4];
        v.x *= scale; v.y *= scale; v.z *= scale; v.w *= scale;
        *(float4*)&Qs[r * 64 + e4 * 4] = v;
    }

    float m[4], l[4], acc[4][4];
#pragma unroll
    for (int i = 0; i < 4; i++) {
        m[i] = -1e30f; l[i] = 0.f;
#pragma unroll
        for (int j = 0; j < 4; j++) acc[i][j] = 0.f;
    }

    const int* maskb = amask + (size_t)b * NSEQ;

    for (int j0 = 0; j0 < NSEQ; j0 += 64) {
        // Load K tile (also serves as V)
#pragma unroll
        for (int it = 0; it < 4; it++) {
            int f = tid + it * 256;
            int r = f / 16, e4 = f % 16;
            *(float4*)&Ks[r * 68 + e4 * 4] =
                *(const float4*)&T[(size_t)(j0 + r) * HD + e4 * 4];
        }
        if (tid < 64) mk[tid] = maskb[j0 + tid];
        __syncthreads();

        // S tile: rows trow*4+i, cols tcol+16*j
        float s[4][4];
#pragma unroll
        for (int i = 0; i < 4; i++)
#pragma unroll
            for (int j = 0; j < 4; j++) s[i][j] = 0.f;

#pragma unroll
        for (int e4 = 0; e4 < 16; e4++) {
            float4 qv[4], kv[4];
#pragma unroll
            for (int i = 0; i < 4; i++)
                qv[i] = *(const float4*)&Qs[(trow * 4 + i) * 64 + e4 * 4];
#pragma unroll
            for (int j = 0; j < 4; j++)
                kv[j] = *(const float4*)&Ks[(tcol + 16 * j) * 68 + e4 * 4];
#pragma unroll
            for (int i = 0; i < 4; i++)
#pragma unroll
                for (int j = 0; j < 4; j++) {
                    s[i][j] = fmaf(qv[i].x, kv[j].x, s[i][j]);
                    s[i][j] = fmaf(qv[i].y, kv[j].y, s[i][j]);
                    s[i][j] = fmaf(qv[i].z, kv[j].z, s[i][j]);
                    s[i][j] = fmaf(qv[i].w, kv[j].w, s[i][j]);
                }
        }

        // mask (key dim)
#pragma unroll
        for (int j = 0; j < 4; j++) {
            if (mk[tcol + 16 * j] == 0) {
#pragma unroll
                for (int i = 0; i < 4; i++) s[i][j] = -1e30f;
            }
        }

        // row max across the 16 lanes sharing trow
        float mt[4];
#pragma unroll
        for (int i = 0; i < 4; i++) {
            mt[i] = s[i][0];
#pragma unroll
            for (int j = 1; j < 4; j++) mt[i] = fmaxf(mt[i], s[i][j]);
        }
#pragma unroll
        for (int off = 1; off < 16; off <<= 1) {
#pragma unroll
            for (int i = 0; i < 4; i++)
                mt[i] = fmaxf(mt[i], __shfl_xor_sync(0xffffffffu, mt[i], off));
        }

        float alpha[4];
#pragma unroll
        for (int i = 0; i < 4; i++) {
            float mn = fmaxf(m[i], mt[i]);
            alpha[i] = __expf(m[i] - mn);
            m[i] = mn;
            l[i] *= alpha[i];
#pragma unroll
            for (int j = 0; j < 4; j++) acc[i][j] *= alpha[i];
        }

        // p = exp(s - m), partial row sums
        float ls[4];
#pragma unroll
        for (int i = 0; i < 4; i++) {
            ls[i] = 0.f;
#pragma unroll
            for (int j = 0; j < 4; j++) {
                float p = __expf(s[i][j] - m[i]);
                s[i][j] = p;
                ls[i] += p;
            }
        }
#pragma unroll
        for (int off = 1; off < 16; off <<= 1) {
#pragma unroll
            for (int i = 0; i < 4; i++)
                ls[i] += __shfl_xor_sync(0xffffffffu, ls[i], off);
        }
#pragma unroll
        for (int i = 0; i < 4; i++) l[i] += ls[i];

        // stage P to smem
#pragma unroll
        for (int i = 0; i < 4; i++)
#pragma unroll
            for (int j = 0; j < 4; j++)
                Ps[(trow * 4 + i) * 64 + tcol + 16 * j] = s[i][j];
        __syncthreads();

        // PV: out cols e = tcol*4 .. +3
#pragma unroll 4
        for (int jj = 0; jj < 64; jj++) {
            float4 v = *(const float4*)&Ks[jj * 68 + tcol * 4];
#pragma unroll
            for (int i = 0; i < 4; i++) {
                float p = Ps[(trow * 4 + i) * 64 + jj];
                acc[i][0] = fmaf(p, v.x, acc[i][0]);
                acc[i][1] = fmaf(p, v.y, acc[i][1]);
                acc[i][2] = fmaf(p, v.z, acc[i][2]);
                acc[i][3] = fmaf(p, v.w, acc[i][3]);
            }
        }
        __syncthreads();
    }

    // epilogue: normalize + write out[b][n][h*64+e]
#pragma unroll
    for (int i = 0; i < 4; i++) {
        float inv = 1.f / l[i];
        int n = q0 + trow * 4 + i;
        float4 o = make_float4(acc[i][0] * inv, acc[i][1] * inv,
                               acc[i][2] * inv, acc[i][3] * inv);
        *(float4*)&out[((size_t)b * NSEQ + n) * (NH * HD) + h * HD + tcol * 4] = o;
    }
}

// ---------------------------------------------------------------------------
extern "C" void kernel_launch(void* const* d_in, const int* in_sizes, int n_in,
                              void* d_out, int out_size) {
    const float* hidden = (const float*)d_in[0];
    const int*   amask  = (const int*)d_in[1];
    const float* Wt     = (const float*)d_in[2];
    const float* Wa     = (const float*)d_in[3];
    float* out = (float*)d_out;

    k_wc<<<dim3(NH, HIDD / 128), 256>>>(Wt, Wa);
    k_proj<<<dim3(NSEQ / 128, NB * NH), 256>>>(hidden);

    size_t smem = (size_t)(64 * 64 + 64 * 68 + 64 * 64) * sizeof(float)
                + 64 * sizeof(int);
    cudaFuncSetAttribute(k_attn, cudaFuncAttributeMaxDynamicSharedMemorySize,
                         (int)smem);
    k_attn<<<dim3(NSEQ / 64, NB * NH), 256, smem>>>(amask, out);
}